// round 5
// baseline (speedup 1.0000x reference)
#include <cuda_runtime.h>
#include <math.h>
#include <stdint.h>

#define KEXP 8

// ---------------- scratch (static device memory; no allocations allowed) ----
__device__ float g_bufA[24780800];    // max: act1 = 128*64*55*55
__device__ float g_bufB[5971968];     // max: pool1 = 128*64*27*27
__device__ float g_wbuf[113246208];   // max: L4 mixed weights; FC scratch later
__device__ float g_pooled[128 * 384];
__device__ float g_r[128 * KEXP];

// FC scratch offsets inside g_wbuf (in floats)
#define POOLT_OFF 0
#define PART_OFF  (2*1024*1024)
#define Y1T_OFF   (7*1024*1024)
#define Y2T_OFF   (8*1024*1024)

// ---------------- packed fp32x2 FMA helpers ----------------------------------
__device__ __forceinline__ unsigned long long pack_dup_f32(float a) {
    unsigned long long p;
    asm("mov.b64 %0, {%1, %1};" : "=l"(p) : "f"(a));
    return p;
}
__device__ __forceinline__ void fma_f32x2(unsigned long long& d, unsigned long long a,
                                          unsigned long long b) {
    asm("fma.rn.f32x2 %0, %1, %2, %0;" : "+l"(d) : "l"(a), "l"(b));
}
__device__ __forceinline__ void unpack_f32x2(unsigned long long p, float& lo, float& hi) {
    asm("mov.b64 {%0, %1}, %2;" : "=f"(lo), "=f"(hi) : "l"(p));
}

// ---------------- tf32 helpers (sm_80+, no arch-specific target needed) ------
__device__ __forceinline__ uint32_t tf32_hi(float x) {
    uint32_t u;
    asm("cvt.rna.tf32.f32 %0, %1;" : "=r"(u) : "f"(x));
    return u;
}
__device__ __forceinline__ void mma_tf32(float* c, const uint32_t* a, const uint32_t* b) {
    asm volatile(
        "mma.sync.aligned.m16n8k8.row.col.f32.tf32.tf32.f32 "
        "{%0,%1,%2,%3}, {%4,%5,%6,%7}, {%8,%9}, {%0,%1,%2,%3};"
        : "+f"(c[0]), "+f"(c[1]), "+f"(c[2]), "+f"(c[3])
        : "r"(a[0]), "r"(a[1]), "r"(a[2]), "r"(a[3]), "r"(b[0]), "r"(b[1]));
}

// ---------------- per-channel global average pool ---------------------------
__global__ void pool_mean_kernel(const float* __restrict__ x, float* __restrict__ pooled,
                                 int Cin, int HW) {
    int c = blockIdx.x, b = blockIdx.y;
    const float* p = x + ((size_t)b * Cin + c) * HW;
    float s = 0.f;
    for (int i = threadIdx.x; i < HW; i += blockDim.x) s += p[i];
    __shared__ float sh[32];
    int lane = threadIdx.x & 31, w = threadIdx.x >> 5;
    #pragma unroll
    for (int o = 16; o > 0; o >>= 1) s += __shfl_down_sync(0xffffffffu, s, o);
    if (lane == 0) sh[w] = s;
    __syncthreads();
    if (w == 0) {
        s = (lane < (int)(blockDim.x >> 5)) ? sh[lane] : 0.f;
        #pragma unroll
        for (int o = 16; o > 0; o >>= 1) s += __shfl_down_sync(0xffffffffu, s, o);
        if (lane == 0) pooled[b * Cin + c] = s / (float)HW;
    }
}

// ---------------- routing ----------------------------------------------------
__global__ void routing_kernel(const float* __restrict__ pooled, const float* __restrict__ rw,
                               const float* __restrict__ rb, float* __restrict__ r, int Cin) {
    int b = blockIdx.x;
    int k = threadIdx.x >> 5, lane = threadIdx.x & 31;
    if (k < KEXP) {
        float s = 0.f;
        for (int c = lane; c < Cin; c += 32) s += pooled[b * Cin + c] * rw[c * KEXP + k];
        #pragma unroll
        for (int o = 16; o > 0; o >>= 1) s += __shfl_down_sync(0xffffffffu, s, o);
        if (lane == 0) r[b * KEXP + k] = 1.f / (1.f + expf(-(s + rb[k])));
    }
}

// ---------------- expert weight mixing ---------------------------------------
__global__ void mixw2_kernel(const float4* __restrict__ w, const float* __restrict__ r,
                             float4* __restrict__ wb, int ws4) {
    __shared__ float rs[8][KEXP];
    int bg = blockIdx.y;
    if (threadIdx.x < 64)
        rs[threadIdx.x >> 3][threadIdx.x & 7] =
            r[(bg * 8 + (threadIdx.x >> 3)) * KEXP + (threadIdx.x & 7)];
    __syncthreads();
    int i = blockIdx.x * blockDim.x + threadIdx.x;
    if (i >= ws4) return;
    float4 wv[KEXP];
    #pragma unroll
    for (int k = 0; k < KEXP; k++) wv[k] = w[(size_t)k * ws4 + i];
    #pragma unroll
    for (int bb = 0; bb < 8; bb++) {
        float4 acc = make_float4(0.f, 0.f, 0.f, 0.f);
        #pragma unroll
        for (int k = 0; k < KEXP; k++) {
            float rk = rs[bb][k];
            acc.x += rk * wv[k].x; acc.y += rk * wv[k].y;
            acc.z += rk * wv[k].z; acc.w += rk * wv[k].w;
        }
        wb[(size_t)(bg * 8 + bb) * ws4 + i] = acc;
    }
}

// ============================================================================
// Split-tf32 HMMA conv (mma.sync.m16n8k8). 256 threads, 8 warps.
// Warp tile 32x32 (mma grid 2x4). CTA tile BM x BN; K chunk = 16 (2 k8 steps).
// D = Ahi*Bhi + Ahi*Blo + Alo*Bhi (fp32 accum) -> rel err ~2^-22/product.
// Smem is fragment-major so frag reads are stride-1 LDS.32 and loader stores
// are STS.128.
// ============================================================================
template <int BM, int BN, int KH, int KW, int S, int P>
__global__ void __launch_bounds__(256) conv_mma_kernel(
    const float* __restrict__ X, const float* __restrict__ WB,
    const float* __restrict__ R, const float* __restrict__ BEXP,
    float* __restrict__ Y, int Cin, int Cout, int H, int W, int OH, int OW) {
    constexpr int KHW = KH * KW;
    constexpr int MT = BM / 16;          // A m-tiles per CTA
    constexpr int NT8 = BN / 8;          // B n-tiles per CTA
    constexpr int A_SZ = BM * 16;        // floats per A matrix per chunk
    constexpr int B_SZ = BN * 16;
    constexpr int STG = 2 * A_SZ + 2 * B_SZ;  // floats per stage (Ahi,Alo,Bhi,Blo)
    constexpr int QA = (BM * 4) / 256;   // float4-quads per thread (A)
    constexpr int QB = (BN * 4) / 256;
    constexpr int WN = BN / 32;          // warps along n

    extern __shared__ float sm[];

    const int tid = threadIdx.x;
    const int wid = tid >> 5, lane = tid & 31;
    const int b = blockIdx.z;
    const int m0 = blockIdx.y * BM, n0 = blockIdx.x * BN;
    const int Ksz = Cin * KHW;   // divisible by 16 for all tc layers
    const int Nn = OH * OW;
    const int nC = Ksz / 16;

    const float* __restrict__ Xb = X + (size_t)b * Cin * H * W;
    const float* __restrict__ Wb = WB + (size_t)b * Cout * Ksz;

    const int warpM = wid / WN, warpN = wid % WN;
    const int tg = lane & 3, g = lane >> 2;

    // ---- per-thread loader geometry (fixed across chunks) ----
    // A: quad qi = tid + q*256 -> m = qi>>2, kq = qi&3 (4 k-floats)
    // B: quad qi -> n = qi>>2, kq = qi&3
    int bn_[QB], boy_[QB], box_[QB];
    bool bnv_[QB];
    #pragma unroll
    for (int q = 0; q < QB; q++) {
        int qi = tid + q * 256;
        int n = qi >> 2;
        int gn = n0 + n;
        bool nv = gn < Nn;
        int oy = nv ? gn / OW : 0;
        int ox = nv ? gn - oy * OW : 0;
        bn_[q] = n; bnv_[q] = nv;
        boy_[q] = oy * S - P; box_[q] = ox * S - P;
    }

    float4 aT[QA];
    float bT[QB][4];

    auto ldg = [&](int kk) {
        #pragma unroll
        for (int q = 0; q < QA; q++) {
            int qi = tid + q * 256;
            int m = qi >> 2, kq = qi & 3;
            float4 v = make_float4(0.f, 0.f, 0.f, 0.f);
            if (m0 + m < Cout)
                v = *reinterpret_cast<const float4*>(Wb + (size_t)(m0 + m) * Ksz + kk + 4 * kq);
            aT[q] = v;
        }
        #pragma unroll
        for (int q = 0; q < QB; q++) {
            int qi = tid + q * 256;
            int kq = qi & 3;
            #pragma unroll
            for (int j = 0; j < 4; j++) {
                int gk = kk + 4 * kq + j;
                float v = 0.f;
                if (bnv_[q]) {
                    int ci = gk / KHW;
                    int rem = gk - ci * KHW;
                    int ky = rem / KW, kx = rem - ky * KW;
                    int iy = boy_[q] + ky, ix = box_[q] + kx;
                    if (iy >= 0 && iy < H && ix >= 0 && ix < W)
                        v = Xb[((size_t)ci * H + iy) * W + ix];
                }
                bT[q][j] = v;
            }
        }
    };

    auto sts = [&](int st) {
        float* base = sm + st * STG;
        #pragma unroll
        for (int q = 0; q < QA; q++) {
            int qi = tid + q * 256;
            int m = qi >> 2, kq = qi & 3;
            int tK = kq >> 1;
            int reg = ((m & 15) >> 3) + 2 * (kq & 1);
            int mTile = m >> 4;
            int idx = ((tK * MT + mTile) * 4 + reg) * 32 + 4 * (m & 7);
            float hx = __uint_as_float(tf32_hi(aT[q].x));
            float hy = __uint_as_float(tf32_hi(aT[q].y));
            float hz = __uint_as_float(tf32_hi(aT[q].z));
            float hw = __uint_as_float(tf32_hi(aT[q].w));
            *reinterpret_cast<float4*>(base + idx) = make_float4(hx, hy, hz, hw);
            float lx = __uint_as_float(tf32_hi(aT[q].x - hx));
            float ly = __uint_as_float(tf32_hi(aT[q].y - hy));
            float lz = __uint_as_float(tf32_hi(aT[q].z - hz));
            float lw = __uint_as_float(tf32_hi(aT[q].w - hw));
            *reinterpret_cast<float4*>(base + A_SZ + idx) = make_float4(lx, ly, lz, lw);
        }
        #pragma unroll
        for (int q = 0; q < QB; q++) {
            int qi = tid + q * 256;
            int n = bn_[q], kq = qi & 3;
            int tK = kq >> 1;
            int reg = kq & 1;
            int nTile = n >> 3;
            int idx = ((tK * NT8 + nTile) * 2 + reg) * 32 + 4 * (n & 7);
            float h0 = __uint_as_float(tf32_hi(bT[q][0]));
            float h1 = __uint_as_float(tf32_hi(bT[q][1]));
            float h2 = __uint_as_float(tf32_hi(bT[q][2]));
            float h3 = __uint_as_float(tf32_hi(bT[q][3]));
            *reinterpret_cast<float4*>(base + 2 * A_SZ + idx) = make_float4(h0, h1, h2, h3);
            float l0 = __uint_as_float(tf32_hi(bT[q][0] - h0));
            float l1 = __uint_as_float(tf32_hi(bT[q][1] - h1));
            float l2 = __uint_as_float(tf32_hi(bT[q][2] - h2));
            float l3 = __uint_as_float(tf32_hi(bT[q][3] - h3));
            *reinterpret_cast<float4*>(base + 2 * A_SZ + B_SZ + idx) = make_float4(l0, l1, l2, l3);
        }
    };

    float acc[2][4][4];
    #pragma unroll
    for (int i = 0; i < 2; i++)
        #pragma unroll
        for (int j = 0; j < 4; j++)
            #pragma unroll
            for (int e = 0; e < 4; e++) acc[i][j][e] = 0.f;

    ldg(0);
    sts(0);
    __syncthreads();

    for (int c = 0; c < nC; c++) {
        if (c + 1 < nC) ldg((c + 1) * 16);
        const float* sb = sm + (c & 1) * STG;
        #pragma unroll
        for (int tK = 0; tK < 2; tK++) {
            uint32_t ah[2][4], bh[4][2], bl[4][2];
            #pragma unroll
            for (int i = 0; i < 2; i++) {
                int mT = warpM * 2 + i;
                #pragma unroll
                for (int rg = 0; rg < 4; rg++)
                    ah[i][rg] = __float_as_uint(sb[((tK * MT + mT) * 4 + rg) * 32 + lane]);
            }
            #pragma unroll
            for (int j = 0; j < 4; j++) {
                int nT = warpN * 4 + j;
                #pragma unroll
                for (int rg = 0; rg < 2; rg++) {
                    bh[j][rg] = __float_as_uint(sb[2 * A_SZ + ((tK * NT8 + nT) * 2 + rg) * 32 + lane]);
                    bl[j][rg] = __float_as_uint(sb[2 * A_SZ + B_SZ + ((tK * NT8 + nT) * 2 + rg) * 32 + lane]);
                }
            }
            // pass 1: Ahi * Bhi
            #pragma unroll
            for (int i = 0; i < 2; i++)
                #pragma unroll
                for (int j = 0; j < 4; j++) mma_tf32(acc[i][j], ah[i], bh[j]);
            // pass 2: Ahi * Blo
            #pragma unroll
            for (int i = 0; i < 2; i++)
                #pragma unroll
                for (int j = 0; j < 4; j++) mma_tf32(acc[i][j], ah[i], bl[j]);
            // reload Alo over ah, pass 3: Alo * Bhi
            #pragma unroll
            for (int i = 0; i < 2; i++) {
                int mT = warpM * 2 + i;
                #pragma unroll
                for (int rg = 0; rg < 4; rg++)
                    ah[i][rg] = __float_as_uint(sb[A_SZ + ((tK * MT + mT) * 4 + rg) * 32 + lane]);
            }
            #pragma unroll
            for (int i = 0; i < 2; i++)
                #pragma unroll
                for (int j = 0; j < 4; j++) mma_tf32(acc[i][j], ah[i], bh[j]);
        }
        if (c + 1 < nC) {
            __syncthreads();
            sts((c + 1) & 1);
            __syncthreads();
        }
    }

    // ---- epilogue: bias + relu + store ----
    float rr[KEXP];
    #pragma unroll
    for (int k = 0; k < KEXP; k++) rr[k] = R[b * KEXP + k];
    #pragma unroll
    for (int i = 0; i < 2; i++) {
        int mA = m0 + warpM * 32 + i * 16 + g;
        int mB = mA + 8;
        float biasA = 0.f, biasB = 0.f;
        if (mA < Cout) {
            #pragma unroll
            for (int k = 0; k < KEXP; k++) biasA += rr[k] * BEXP[k * Cout + mA];
        }
        if (mB < Cout) {
            #pragma unroll
            for (int k = 0; k < KEXP; k++) biasB += rr[k] * BEXP[k * Cout + mB];
        }
        float* YA = Y + ((size_t)b * Cout + mA) * Nn;
        float* YB = Y + ((size_t)b * Cout + mB) * Nn;
        #pragma unroll
        for (int j = 0; j < 4; j++) {
            int nb = n0 + warpN * 32 + j * 8 + 2 * tg;
            if (mA < Cout) {
                if (nb < Nn) { float v = acc[i][j][0] + biasA; YA[nb] = v > 0.f ? v : 0.f; }
                if (nb + 1 < Nn) { float v = acc[i][j][1] + biasA; YA[nb + 1] = v > 0.f ? v : 0.f; }
            }
            if (mB < Cout) {
                if (nb < Nn) { float v = acc[i][j][2] + biasB; YB[nb] = v > 0.f ? v : 0.f; }
                if (nb + 1 < Nn) { float v = acc[i][j][3] + biasB; YB[nb + 1] = v > 0.f ? v : 0.f; }
            }
        }
    }
}

// ---------------- SIMT conv (layer 1 only, f32x2) ----------------------------
template <int BM, int BN, int KH, int KW, int S, int P, bool AVEC>
__global__ void __launch_bounds__(BM * BN / 64) conv2_kernel(
    const float* __restrict__ X, const float* __restrict__ WB,
    const float* __restrict__ R, const float* __restrict__ BEXP,
    float* __restrict__ Y, int Cin, int Cout, int H, int W, int OH, int OW) {
    constexpr int BK = 16, TM = 8, TN = 8;
    constexpr int TH = BM * BN / (TM * TN);
    constexpr int KHW = KH * KW;
    constexpr int A4 = BM * BK / (4 * TH);
    constexpr int BL = BN * BK / TH;
    constexpr int BKP = TH / BN;

    __shared__ float As[2][BK][BM + 4];
    __shared__ float Bs[2][BK][BN + 4];

    const int b = blockIdx.z;
    const int m0 = blockIdx.y * BM, n0 = blockIdx.x * BN;
    const int Ksz = Cin * KHW;
    const int Nn = OH * OW;
    const int tid = threadIdx.x;

    const float* __restrict__ Xb = X + (size_t)b * Cin * H * W;
    const float* __restrict__ Wb = WB + (size_t)b * Cout * Ksz;

    const int nb = tid % BN;
    const int gnb = n0 + nb;
    const bool nv = gnb < Nn;
    const int oyb = nv ? gnb / OW : 0;
    const int oxb = nv ? gnb - oyb * OW : 0;
    const int iy0 = oyb * S - P, ix0 = oxb * S - P;
    const int kb0 = tid / BN;

    float4 aT[A4];
    float bT[BL];

    auto ldg = [&](int kk) {
        #pragma unroll
        for (int p = 0; p < A4; p++) {
            int e = tid + p * TH;
            int m = e >> 2, gk = kk + (e & 3) * 4;
            float4 v = make_float4(0.f, 0.f, 0.f, 0.f);
            if (m0 + m < Cout) {
                if (AVEC && gk + 3 < Ksz) {
                    v = *reinterpret_cast<const float4*>(Wb + (size_t)(m0 + m) * Ksz + gk);
                } else {
                    float* pv = (float*)&v;
                    #pragma unroll
                    for (int i = 0; i < 4; i++)
                        if (gk + i < Ksz) pv[i] = Wb[(size_t)(m0 + m) * Ksz + gk + i];
                }
            }
            aT[p] = v;
        }
        #pragma unroll
        for (int p = 0; p < BL; p++) {
            int k = kb0 + p * BKP;
            int gk = kk + k;
            float v = 0.f;
            if (nv && gk < Ksz) {
                int ci = gk / KHW;
                int rem = gk - ci * KHW;
                int ky = rem / KW, kx = rem - ky * KW;
                int iy = iy0 + ky, ix = ix0 + kx;
                if (iy >= 0 && iy < H && ix >= 0 && ix < W)
                    v = Xb[((size_t)ci * H + iy) * W + ix];
            }
            bT[p] = v;
        }
    };
    auto sts = [&](int buf) {
        #pragma unroll
        for (int p = 0; p < A4; p++) {
            int e = tid + p * TH;
            int m = e >> 2, k = (e & 3) * 4;
            As[buf][k + 0][m] = aT[p].x;
            As[buf][k + 1][m] = aT[p].y;
            As[buf][k + 2][m] = aT[p].z;
            As[buf][k + 3][m] = aT[p].w;
        }
        #pragma unroll
        for (int p = 0; p < BL; p++) Bs[buf][kb0 + p * BKP][nb] = bT[p];
    };

    const int tx = tid % (BN / TN);
    const int ty = tid / (BN / TN);

    unsigned long long acc2[TM][TN / 2];
    #pragma unroll
    for (int i = 0; i < TM; i++)
        #pragma unroll
        for (int j = 0; j < TN / 2; j++) acc2[i][j] = 0ull;

    const int nT = (Ksz + BK - 1) / BK;
    ldg(0);
    sts(0);
    __syncthreads();

    for (int kt = 0; kt < nT; kt++) {
        int cur = kt & 1;
        if (kt + 1 < nT) ldg((kt + 1) * BK);
        #pragma unroll
        for (int kq = 0; kq < BK; kq++) {
            float4 a0 = *(const float4*)&As[cur][kq][ty * TM];
            float4 a1 = *(const float4*)&As[cur][kq][ty * TM + 4];
            const ulonglong2* pb = (const ulonglong2*)&Bs[cur][kq][tx * TN];
            ulonglong2 q0 = pb[0], q1 = pb[1];
            unsigned long long b2[4] = {q0.x, q0.y, q1.x, q1.y};
            float ar[8] = {a0.x, a0.y, a0.z, a0.w, a1.x, a1.y, a1.z, a1.w};
            #pragma unroll
            for (int i = 0; i < TM; i++) {
                unsigned long long af = pack_dup_f32(ar[i]);
                #pragma unroll
                for (int j = 0; j < TN / 2; j++) fma_f32x2(acc2[i][j], af, b2[j]);
            }
        }
        if (kt + 1 < nT) {
            sts(cur ^ 1);
            __syncthreads();
        }
    }

    float rr[KEXP];
    #pragma unroll
    for (int k = 0; k < KEXP; k++) rr[k] = R[b * KEXP + k];
    #pragma unroll
    for (int i = 0; i < TM; i++) {
        int gm = m0 + ty * TM + i;
        if (gm < Cout) {
            float bias = 0.f;
            #pragma unroll
            for (int k = 0; k < KEXP; k++) bias += rr[k] * BEXP[k * Cout + gm];
            float* Yp = Y + ((size_t)b * Cout + gm) * Nn;
            #pragma unroll
            for (int j = 0; j < TN / 2; j++) {
                float lo, hi;
                unpack_f32x2(acc2[i][j], lo, hi);
                int gn = n0 + tx * TN + 2 * j;
                if (gn < Nn) {
                    float v = lo + bias;
                    Yp[gn] = v > 0.f ? v : 0.f;
                }
                if (gn + 1 < Nn) {
                    float v = hi + bias;
                    Yp[gn + 1] = v > 0.f ? v : 0.f;
                }
            }
        }
    }
}

// ---------------- FC split-K partial GEMM (transposed, f32x2) ---------------
__global__ void __launch_bounds__(256) fc_partial_kernel(
    const float* __restrict__ Wm, const float* __restrict__ Xt,
    float* __restrict__ Part, int Nout, int Npad, int Kchunk) {
    constexpr int BM = 128, BN = 128, BK = 16, TM = 8, TN = 8;
    __shared__ float As[2][BK][BM + 4];
    __shared__ float Bs[2][BK][BN + 4];
    const int m0 = blockIdx.x * BM;
    const int ks = blockIdx.y;
    const int kbase = ks * Kchunk;
    const int tid = threadIdx.x;

    const int ma = tid % BM;
    const int ka = tid / BM;
    const bool mvalid = (m0 + ma) < Nout;

    float aT[8], bT[8];
    auto ldg = [&](int kk) {
        #pragma unroll
        for (int p = 0; p < 8; p++) {
            int gk = kbase + kk + ka + 2 * p;
            aT[p] = mvalid ? Wm[(size_t)gk * Nout + m0 + ma] : 0.f;
            bT[p] = Xt[(size_t)gk * 128 + ma];
        }
    };
    auto sts = [&](int buf) {
        #pragma unroll
        for (int p = 0; p < 8; p++) {
            int k = ka + 2 * p;
            As[buf][k][ma] = aT[p];
            Bs[buf][k][ma] = bT[p];
        }
    };

    const int tx = tid % (BN / TN);
    const int ty = tid / (BN / TN);
    unsigned long long acc2[TM][TN / 2];
    #pragma unroll
    for (int i = 0; i < TM; i++)
        #pragma unroll
        for (int j = 0; j < TN / 2; j++) acc2[i][j] = 0ull;

    const int nT = Kchunk / BK;
    ldg(0);
    sts(0);
    __syncthreads();
    for (int kt = 0; kt < nT; kt++) {
        int cur = kt & 1;
        if (kt + 1 < nT) ldg((kt + 1) * BK);
        #pragma unroll
        for (int kq = 0; kq < BK; kq++) {
            float4 a0 = *(const float4*)&As[cur][kq][ty * TM];
            float4 a1 = *(const float4*)&As[cur][kq][ty * TM + 4];
            const ulonglong2* pb = (const ulonglong2*)&Bs[cur][kq][tx * TN];
            ulonglong2 q0 = pb[0], q1 = pb[1];
            unsigned long long b2[4] = {q0.x, q0.y, q1.x, q1.y};
            float ar[8] = {a0.x, a0.y, a0.z, a0.w, a1.x, a1.y, a1.z, a1.w};
            #pragma unroll
            for (int i = 0; i < TM; i++) {
                unsigned long long af = pack_dup_f32(ar[i]);
                #pragma unroll
                for (int j = 0; j < TN / 2; j++) fma_f32x2(acc2[i][j], af, b2[j]);
            }
        }
        if (kt + 1 < nT) {
            sts(cur ^ 1);
            __syncthreads();
        }
    }
    #pragma unroll
    for (int i = 0; i < TM; i++) {
        size_t rrow = (size_t)ks * Npad + m0 + ty * TM + i;
        #pragma unroll
        for (int j = 0; j < TN / 2; j++) {
            float lo, hi;
            unpack_f32x2(acc2[i][j], lo, hi);
            Part[rrow * 128 + tx * TN + 2 * j] = lo;
            Part[rrow * 128 + tx * TN + 2 * j + 1] = hi;
        }
    }
}

__global__ void fc_reduce_kernel(const float* __restrict__ Part, const float* __restrict__ bias,
                                 float* __restrict__ Yt, int Nout, int Npad, int S) {
    int idx = blockIdx.x * blockDim.x + threadIdx.x;
    if (idx >= Nout * 128) return;
    int n = idx >> 7, bb = idx & 127;
    float s = 0.f;
    for (int si = 0; si < S; si++) s += Part[((size_t)si * Npad + n) * 128 + bb];
    float v = s + bias[n];
    Yt[idx] = v > 0.f ? v : 0.f;
}

__global__ void fc_reduce_out_kernel(const float* __restrict__ Part, const float* __restrict__ bias,
                                     float* __restrict__ out, int Nout, int Npad, int S) {
    int idx = blockIdx.x * blockDim.x + threadIdx.x;
    if (idx >= Nout * 128) return;
    int n = idx >> 7, bb = idx & 127;
    float s = 0.f;
    for (int si = 0; si < S; si++) s += Part[((size_t)si * Npad + n) * 128 + bb];
    out[(size_t)bb * Nout + n] = s + bias[n];
}

// ---------------- maxpools ---------------------------------------------------
__global__ void maxpool_kernel(const float* __restrict__ x, float* __restrict__ y,
                               int BC, int H, int W, int OH, int OW) {
    int idx = blockIdx.x * blockDim.x + threadIdx.x;
    int total = BC * OH * OW;
    if (idx >= total) return;
    int ox = idx % OW; int t = idx / OW;
    int oy = t % OH; int bc = t / OH;
    const float* p = x + ((size_t)bc * H + oy * 2) * W + ox * 2;
    float m = -INFINITY;
    #pragma unroll
    for (int i = 0; i < 3; i++)
        #pragma unroll
        for (int j = 0; j < 3; j++) {
            float v = p[i * W + j];
            m = v > m ? v : m;
        }
    y[idx] = m;
}

__global__ void maxpoolT_kernel(const float* __restrict__ x, float* __restrict__ yt,
                                int C, int H, int W, int OH, int OW) {
    int idx = blockIdx.x * blockDim.x + threadIdx.x;
    int total = 128 * C * OH * OW;
    if (idx >= total) return;
    int ox = idx % OW; int t = idx / OW;
    int oy = t % OH; t /= OH;
    int c = t % C; int b = t / C;
    const float* p = x + (((size_t)b * C + c) * H + oy * 2) * W + ox * 2;
    float m = -INFINITY;
    #pragma unroll
    for (int i = 0; i < 3; i++)
        #pragma unroll
        for (int j = 0; j < 3; j++) {
            float v = p[i * W + j];
            m = v > m ? v : m;
        }
    yt[((size_t)(c * OH + oy) * OW + ox) * 128 + b] = m;
}

// ---------------- driver -----------------------------------------------------
static inline int ceil_div(int a, int b) { return (a + b - 1) / b; }

#define MMA_SMEM (256 * 192)  // 2 stages * 32*(BM+BN) floats * 4B = 49152 for both configs

extern "C" void kernel_launch(void* const* d_in, const int* in_sizes, int n_in,
                              void* d_out, int out_size) {
    const float* x = (const float*)d_in[0];
    const float *w[5], *bexp[5], *rw[5], *rb[5];
    for (int l = 0; l < 5; l++) {
        w[l]    = (const float*)d_in[1 + 4 * l];
        bexp[l] = (const float*)d_in[2 + 4 * l];
        rw[l]   = (const float*)d_in[3 + 4 * l];
        rb[l]   = (const float*)d_in[4 + 4 * l];
    }
    const float* fw1 = (const float*)d_in[21]; const float* fb1 = (const float*)d_in[22];
    const float* fw2 = (const float*)d_in[23]; const float* fb2 = (const float*)d_in[24];
    const float* fw3 = (const float*)d_in[25]; const float* fb3 = (const float*)d_in[26];

    float *bufA, *bufB, *wbuf, *pooled, *r;
    cudaGetSymbolAddress((void**)&bufA, g_bufA);
    cudaGetSymbolAddress((void**)&bufB, g_bufB);
    cudaGetSymbolAddress((void**)&wbuf, g_wbuf);
    cudaGetSymbolAddress((void**)&pooled, g_pooled);
    cudaGetSymbolAddress((void**)&r, g_r);

    cudaFuncSetAttribute(conv_mma_kernel<64, 128, 5, 5, 1, 2>,
                         cudaFuncAttributeMaxDynamicSharedMemorySize, MMA_SMEM);
    cudaFuncSetAttribute(conv_mma_kernel<128, 64, 3, 3, 1, 1>,
                         cudaFuncAttributeMaxDynamicSharedMemorySize, MMA_SMEM);

    const int B = 128;

    // ===== Layer 1: CondConv 3->64, k=11, s=4, p=2 (SIMT fp32) : 224->55, pool->27
    pool_mean_kernel<<<dim3(3, B), 256>>>(x, pooled, 3, 224 * 224);
    routing_kernel<<<B, 256>>>(pooled, rw[0], rb[0], r, 3);
    {
        int ws4 = 64 * 3 * 121 / 4;
        mixw2_kernel<<<dim3(ceil_div(ws4, 256), B / 8), 256>>>((const float4*)w[0], r, (float4*)wbuf, ws4);
    }
    conv2_kernel<64, 128, 11, 11, 4, 2, false><<<dim3(24, 1, B), 128>>>(
        x, wbuf, r, bexp[0], bufA, 3, 64, 224, 224, 55, 55);
    maxpool_kernel<<<ceil_div(B * 64 * 27 * 27, 256), 256>>>(bufA, bufB, B * 64, 55, 55, 27, 27);

    // ===== Layer 2: CondConv 64->192, k=5, p=2 (HMMA split-tf32) : 27->27, pool->13
    pool_mean_kernel<<<dim3(64, B), 256>>>(bufB, pooled, 64, 27 * 27);
    routing_kernel<<<B, 256>>>(pooled, rw[1], rb[1], r, 64);
    {
        int ws4 = 192 * 64 * 25 / 4;
        mixw2_kernel<<<dim3(ceil_div(ws4, 256), B / 8), 256>>>((const float4*)w[1], r, (float4*)wbuf, ws4);
    }
    conv_mma_kernel<64, 128, 5, 5, 1, 2><<<dim3(6, 3, B), 256, MMA_SMEM>>>(
        bufB, wbuf, r, bexp[1], bufA, 64, 192, 27, 27, 27, 27);
    maxpool_kernel<<<ceil_div(B * 192 * 13 * 13, 256), 256>>>(bufA, bufB, B * 192, 27, 27, 13, 13);

    // ===== Layer 3: CondConv 192->384, k=3, p=1 (HMMA) : 13->13
    pool_mean_kernel<<<dim3(192, B), 256>>>(bufB, pooled, 192, 13 * 13);
    routing_kernel<<<B, 256>>>(pooled, rw[2], rb[2], r, 192);
    {
        int ws4 = 384 * 192 * 9 / 4;
        mixw2_kernel<<<dim3(ceil_div(ws4, 256), B / 8), 256>>>((const float4*)w[2], r, (float4*)wbuf, ws4);
    }
    conv_mma_kernel<128, 64, 3, 3, 1, 1><<<dim3(3, 3, B), 256, MMA_SMEM>>>(
        bufB, wbuf, r, bexp[2], bufA, 192, 384, 13, 13, 13, 13);

    // ===== Layer 4: CondConv 384->256, k=3, p=1 (HMMA) : 13->13
    pool_mean_kernel<<<dim3(384, B), 256>>>(bufA, pooled, 384, 13 * 13);
    routing_kernel<<<B, 256>>>(pooled, rw[3], rb[3], r, 384);
    {
        int ws4 = 256 * 384 * 9 / 4;
        mixw2_kernel<<<dim3(ceil_div(ws4, 256), B / 8), 256>>>((const float4*)w[3], r, (float4*)wbuf, ws4);
    }
    conv_mma_kernel<128, 64, 3, 3, 1, 1><<<dim3(3, 2, B), 256, MMA_SMEM>>>(
        bufA, wbuf, r, bexp[3], bufB, 384, 256, 13, 13, 13, 13);

    // ===== Layer 5: CondConv 256->256, k=3, p=1 (HMMA) : 13->13, pool->6
    pool_mean_kernel<<<dim3(256, B), 256>>>(bufB, pooled, 256, 13 * 13);
    routing_kernel<<<B, 256>>>(pooled, rw[4], rb[4], r, 256);
    {
        int ws4 = 256 * 256 * 9 / 4;
        mixw2_kernel<<<dim3(ceil_div(ws4, 256), B / 8), 256>>>((const float4*)w[4], r, (float4*)wbuf, ws4);
    }
    conv_mma_kernel<128, 64, 3, 3, 1, 1><<<dim3(3, 2, B), 256, MMA_SMEM>>>(
        bufB, wbuf, r, bexp[4], bufA, 256, 256, 13, 13, 13, 13);

    // final pool -> transposed activations [9216][128]
    maxpoolT_kernel<<<ceil_div(B * 256 * 36, 256), 256>>>(bufA, wbuf + POOLT_OFF, 256, 13, 13, 6, 6);

    // ===== FC head (fp32, split-K) ==========================================
    fc_partial_kernel<<<dim3(32, 8), 256>>>(fw1, wbuf + POOLT_OFF, wbuf + PART_OFF,
                                            4096, 4096, 1152);
    fc_reduce_kernel<<<ceil_div(4096 * 128, 256), 256>>>(wbuf + PART_OFF, fb1,
                                                         wbuf + Y1T_OFF, 4096, 4096, 8);
    fc_partial_kernel<<<dim3(32, 8), 256>>>(fw2, wbuf + Y1T_OFF, wbuf + PART_OFF,
                                            4096, 4096, 512);
    fc_reduce_kernel<<<ceil_div(4096 * 128, 256), 256>>>(wbuf + PART_OFF, fb2,
                                                         wbuf + Y2T_OFF, 4096, 4096, 8);
    fc_partial_kernel<<<dim3(8, 8), 256>>>(fw3, wbuf + Y2T_OFF, wbuf + PART_OFF,
                                           1000, 1024, 512);
    fc_reduce_out_kernel<<<ceil_div(1000 * 128, 256), 256>>>(wbuf + PART_OFF, fb3,
                                                             (float*)d_out, 1000, 1024, 8);
}

// round 6
// speedup vs baseline: 1.4768x; 1.4768x over previous
#include <cuda_runtime.h>
#include <math.h>
#include <stdint.h>

#define KEXP 8

// ---------------- scratch (static device memory; no allocations allowed) ----
__device__ float g_bufA[24780800];    // max: act1 = 128*64*55*55
__device__ float g_bufB[5971968];     // max: pool1 = 128*64*27*27
__device__ float g_wbuf[113246208];   // max: L4 mixed weights; FC scratch later
__device__ float g_pooled[128 * 384];
__device__ float g_r[128 * KEXP];

// FC scratch offsets inside g_wbuf (in floats)
#define POOLT_OFF 0
#define PART_OFF  (2*1024*1024)
#define Y1T_OFF   (7*1024*1024)
#define Y2T_OFF   (8*1024*1024)

// ---------------- packed fp32x2 FMA helpers ----------------------------------
__device__ __forceinline__ unsigned long long pack_dup_f32(float a) {
    unsigned long long p;
    asm("mov.b64 %0, {%1, %1};" : "=l"(p) : "f"(a));
    return p;
}
__device__ __forceinline__ void fma_f32x2(unsigned long long& d, unsigned long long a,
                                          unsigned long long b) {
    asm("fma.rn.f32x2 %0, %1, %2, %0;" : "+l"(d) : "l"(a), "l"(b));
}
__device__ __forceinline__ void unpack_f32x2(unsigned long long p, float& lo, float& hi) {
    asm("mov.b64 {%0, %1}, %2;" : "=f"(lo), "=f"(hi) : "l"(p));
}

// ---------------- cp.async helpers (sm_80+, arch-generic) --------------------
__device__ __forceinline__ uint32_t smem_u32(const void* p) {
    uint32_t a;
    asm("{ .reg .u64 t; cvta.to.shared.u64 t, %1; cvt.u32.u64 %0, t; }" : "=r"(a) : "l"(p));
    return a;
}
__device__ __forceinline__ void cp_async4(uint32_t dst, const void* src, int sz) {
    asm volatile("cp.async.ca.shared.global [%0], [%1], 4, %2;"
                 :: "r"(dst), "l"(src), "r"(sz) : "memory");
}
#define CP_COMMIT() asm volatile("cp.async.commit_group;" ::: "memory")
#define CP_WAIT(n)  asm volatile("cp.async.wait_group %0;" :: "n"(n) : "memory")

// ---------------- per-channel global average pool ---------------------------
__global__ void pool_mean_kernel(const float* __restrict__ x, float* __restrict__ pooled,
                                 int Cin, int HW) {
    int c = blockIdx.x, b = blockIdx.y;
    const float* p = x + ((size_t)b * Cin + c) * HW;
    float s = 0.f;
    for (int i = threadIdx.x; i < HW; i += blockDim.x) s += p[i];
    __shared__ float sh[32];
    int lane = threadIdx.x & 31, w = threadIdx.x >> 5;
    #pragma unroll
    for (int o = 16; o > 0; o >>= 1) s += __shfl_down_sync(0xffffffffu, s, o);
    if (lane == 0) sh[w] = s;
    __syncthreads();
    if (w == 0) {
        s = (lane < (int)(blockDim.x >> 5)) ? sh[lane] : 0.f;
        #pragma unroll
        for (int o = 16; o > 0; o >>= 1) s += __shfl_down_sync(0xffffffffu, s, o);
        if (lane == 0) pooled[b * Cin + c] = s / (float)HW;
    }
}

// ---------------- routing ----------------------------------------------------
__global__ void routing_kernel(const float* __restrict__ pooled, const float* __restrict__ rw,
                               const float* __restrict__ rb, float* __restrict__ r, int Cin) {
    int b = blockIdx.x;
    int k = threadIdx.x >> 5, lane = threadIdx.x & 31;
    if (k < KEXP) {
        float s = 0.f;
        for (int c = lane; c < Cin; c += 32) s += pooled[b * Cin + c] * rw[c * KEXP + k];
        #pragma unroll
        for (int o = 16; o > 0; o >>= 1) s += __shfl_down_sync(0xffffffffu, s, o);
        if (lane == 0) r[b * KEXP + k] = 1.f / (1.f + expf(-(s + rb[k])));
    }
}

// ---------------- expert weight mixing ---------------------------------------
__global__ void mixw2_kernel(const float4* __restrict__ w, const float* __restrict__ r,
                             float4* __restrict__ wb, int ws4) {
    __shared__ float rs[8][KEXP];
    int bg = blockIdx.y;
    if (threadIdx.x < 64)
        rs[threadIdx.x >> 3][threadIdx.x & 7] =
            r[(bg * 8 + (threadIdx.x >> 3)) * KEXP + (threadIdx.x & 7)];
    __syncthreads();
    int i = blockIdx.x * blockDim.x + threadIdx.x;
    if (i >= ws4) return;
    float4 wv[KEXP];
    #pragma unroll
    for (int k = 0; k < KEXP; k++) wv[k] = w[(size_t)k * ws4 + i];
    #pragma unroll
    for (int bb = 0; bb < 8; bb++) {
        float4 acc = make_float4(0.f, 0.f, 0.f, 0.f);
        #pragma unroll
        for (int k = 0; k < KEXP; k++) {
            float rk = rs[bb][k];
            acc.x += rk * wv[k].x; acc.y += rk * wv[k].y;
            acc.z += rk * wv[k].z; acc.w += rk * wv[k].w;
        }
        wb[(size_t)(bg * 8 + bb) * ws4 + i] = acc;
    }
}

// ============================================================================
// SIMT conv implicit GEMM, f32x2 FMA, cp.async double-buffered loaders.
// 128 threads, BM x BN tile, TM=TN=8.
// ============================================================================
template <int BM, int BN, int KH, int KW, int S, int P>
__global__ void __launch_bounds__(128, 5) conv_ca_kernel(
    const float* __restrict__ X, const float* __restrict__ WB,
    const float* __restrict__ R, const float* __restrict__ BEXP,
    float* __restrict__ Y, int Cin, int Cout, int H, int W, int OH, int OW) {
    constexpr int BK = 16, TM = 8, TN = 8;
    constexpr int KHW = KH * KW;
    constexpr int AP = BM * BK / (4 * 128);  // 4-k groups per thread (A)
    constexpr int BP = BN * BK / 128;        // scalar k's per thread (B)

    __shared__ float As[2][BK][BM + 4];
    __shared__ float Bs[2][BK][BN + 4];

    const int b = blockIdx.z;
    const int m0 = blockIdx.y * BM, n0 = blockIdx.x * BN;
    const int Ksz = Cin * KHW;
    const int Nn = OH * OW;
    const int tid = threadIdx.x;

    const float* __restrict__ Xb = X + (size_t)b * Cin * H * W;
    const float* __restrict__ Wb = WB + (size_t)b * Cout * Ksz;

    // B loader geometry: fixed n per thread, BP consecutive k
    const int nb = tid % BN;
    const int kb0 = (tid / BN) * BP;
    const int gnb = n0 + nb;
    const bool nv = gnb < Nn;
    const int oyb = nv ? gnb / OW : 0;
    const int oxb = nv ? gnb - oyb * OW : 0;
    const int iy0 = oyb * S - P, ix0 = oxb * S - P;

    const uint32_t aAddr = smem_u32(&As[0][0][0]);
    const uint32_t bAddr = smem_u32(&Bs[0][0][0]);
    constexpr uint32_t ASTG = BK * (BM + 4) * 4;
    constexpr uint32_t BSTG = BK * (BN + 4) * 4;

    auto load_stage = [&](int kk, int buf) {
        const uint32_t ad = aAddr + buf * ASTG;
        const uint32_t bd = bAddr + buf * BSTG;
        // A: e-mapping keeps 4 consecutive k per lane -> 8 gmem lines / inst
        #pragma unroll
        for (int p = 0; p < AP; p++) {
            int e = tid + p * 128;
            int m = e >> 2, k4 = (e & 3) * 4;
            const float* wrow = Wb + (size_t)(m0 + m) * Ksz;
            bool mv = (m0 + m) < Cout;
            #pragma unroll
            for (int j = 0; j < 4; j++) {
                int k = k4 + j, gk = kk + k;
                bool v = mv && gk < Ksz;
                cp_async4(ad + (uint32_t)(k * (BM + 4) + m) * 4,
                          v ? (wrow + gk) : (const float*)Wb, v ? 4 : 0);
            }
        }
        // B: im2col gather (zero-fill OOB via src-size 0)
        #pragma unroll
        for (int p = 0; p < BP; p++) {
            int k = kb0 + p, gk = kk + k;
            int ci = gk / KHW;
            int rem = gk - ci * KHW;
            int ky = rem / KW, kx = rem - ky * KW;
            int iy = iy0 + ky, ix = ix0 + kx;
            bool v = nv && gk < Ksz && iy >= 0 && iy < H && ix >= 0 && ix < W;
            cp_async4(bd + (uint32_t)(k * (BN + 4) + nb) * 4,
                      v ? &Xb[((size_t)ci * H + iy) * W + ix] : (const float*)X, v ? 4 : 0);
        }
        CP_COMMIT();
    };

    const int tx = tid % (BN / TN);
    const int ty = tid / (BN / TN);

    unsigned long long acc2[TM][TN / 2];
    #pragma unroll
    for (int i = 0; i < TM; i++)
        #pragma unroll
        for (int j = 0; j < TN / 2; j++) acc2[i][j] = 0ull;

    const int nT = (Ksz + BK - 1) / BK;
    load_stage(0, 0);

    for (int kt = 0; kt < nT; kt++) {
        if (kt + 1 < nT) {
            load_stage((kt + 1) * BK, (kt + 1) & 1);
            CP_WAIT(1);
        } else {
            CP_WAIT(0);
        }
        __syncthreads();
        const int cur = kt & 1;
        #pragma unroll
        for (int kq = 0; kq < BK; kq++) {
            float4 a0 = *(const float4*)&As[cur][kq][ty * TM];
            float4 a1 = *(const float4*)&As[cur][kq][ty * TM + 4];
            const ulonglong2* pb = (const ulonglong2*)&Bs[cur][kq][tx * TN];
            ulonglong2 q0 = pb[0], q1 = pb[1];
            unsigned long long b2[4] = {q0.x, q0.y, q1.x, q1.y};
            float ar[8] = {a0.x, a0.y, a0.z, a0.w, a1.x, a1.y, a1.z, a1.w};
            #pragma unroll
            for (int i = 0; i < TM; i++) {
                unsigned long long af = pack_dup_f32(ar[i]);
                #pragma unroll
                for (int j = 0; j < TN / 2; j++) fma_f32x2(acc2[i][j], af, b2[j]);
            }
        }
        __syncthreads();
    }

    float rr[KEXP];
    #pragma unroll
    for (int k = 0; k < KEXP; k++) rr[k] = R[b * KEXP + k];
    #pragma unroll
    for (int i = 0; i < TM; i++) {
        int gm = m0 + ty * TM + i;
        if (gm < Cout) {
            float bias = 0.f;
            #pragma unroll
            for (int k = 0; k < KEXP; k++) bias += rr[k] * BEXP[k * Cout + gm];
            float* Yp = Y + ((size_t)b * Cout + gm) * Nn;
            #pragma unroll
            for (int j = 0; j < TN / 2; j++) {
                float lo, hi;
                unpack_f32x2(acc2[i][j], lo, hi);
                int gn = n0 + tx * TN + 2 * j;
                if (gn < Nn) {
                    float v = lo + bias;
                    Yp[gn] = v > 0.f ? v : 0.f;
                }
                if (gn + 1 < Nn) {
                    float v = hi + bias;
                    Yp[gn + 1] = v > 0.f ? v : 0.f;
                }
            }
        }
    }
}

// ---------------- FC split-K partial GEMM (transposed, f32x2) ---------------
__global__ void __launch_bounds__(256) fc_partial_kernel(
    const float* __restrict__ Wm, const float* __restrict__ Xt,
    float* __restrict__ Part, int Nout, int Npad, int Kchunk) {
    constexpr int BM = 128, BN = 128, BK = 16, TM = 8, TN = 8;
    __shared__ float As[2][BK][BM + 4];
    __shared__ float Bs[2][BK][BN + 4];
    const int m0 = blockIdx.x * BM;
    const int ks = blockIdx.y;
    const int kbase = ks * Kchunk;
    const int tid = threadIdx.x;

    const int ma = tid % BM;
    const int ka = tid / BM;
    const bool mvalid = (m0 + ma) < Nout;

    float aT[8], bT[8];
    auto ldg = [&](int kk) {
        #pragma unroll
        for (int p = 0; p < 8; p++) {
            int gk = kbase + kk + ka + 2 * p;
            aT[p] = mvalid ? Wm[(size_t)gk * Nout + m0 + ma] : 0.f;
            bT[p] = Xt[(size_t)gk * 128 + ma];
        }
    };
    auto sts = [&](int buf) {
        #pragma unroll
        for (int p = 0; p < 8; p++) {
            int k = ka + 2 * p;
            As[buf][k][ma] = aT[p];
            Bs[buf][k][ma] = bT[p];
        }
    };

    const int tx = tid % (BN / TN);
    const int ty = tid / (BN / TN);
    unsigned long long acc2[TM][TN / 2];
    #pragma unroll
    for (int i = 0; i < TM; i++)
        #pragma unroll
        for (int j = 0; j < TN / 2; j++) acc2[i][j] = 0ull;

    const int nT = Kchunk / BK;
    ldg(0);
    sts(0);
    __syncthreads();
    for (int kt = 0; kt < nT; kt++) {
        int cur = kt & 1;
        if (kt + 1 < nT) ldg((kt + 1) * BK);
        #pragma unroll
        for (int kq = 0; kq < BK; kq++) {
            float4 a0 = *(const float4*)&As[cur][kq][ty * TM];
            float4 a1 = *(const float4*)&As[cur][kq][ty * TM + 4];
            const ulonglong2* pb = (const ulonglong2*)&Bs[cur][kq][tx * TN];
            ulonglong2 q0 = pb[0], q1 = pb[1];
            unsigned long long b2[4] = {q0.x, q0.y, q1.x, q1.y};
            float ar[8] = {a0.x, a0.y, a0.z, a0.w, a1.x, a1.y, a1.z, a1.w};
            #pragma unroll
            for (int i = 0; i < TM; i++) {
                unsigned long long af = pack_dup_f32(ar[i]);
                #pragma unroll
                for (int j = 0; j < TN / 2; j++) fma_f32x2(acc2[i][j], af, b2[j]);
            }
        }
        if (kt + 1 < nT) {
            sts(cur ^ 1);
            __syncthreads();
        }
    }
    #pragma unroll
    for (int i = 0; i < TM; i++) {
        size_t rrow = (size_t)ks * Npad + m0 + ty * TM + i;
        #pragma unroll
        for (int j = 0; j < TN / 2; j++) {
            float lo, hi;
            unpack_f32x2(acc2[i][j], lo, hi);
            Part[rrow * 128 + tx * TN + 2 * j] = lo;
            Part[rrow * 128 + tx * TN + 2 * j + 1] = hi;
        }
    }
}

__global__ void fc_reduce_kernel(const float* __restrict__ Part, const float* __restrict__ bias,
                                 float* __restrict__ Yt, int Nout, int Npad, int S) {
    int idx = blockIdx.x * blockDim.x + threadIdx.x;
    if (idx >= Nout * 128) return;
    int n = idx >> 7, bb = idx & 127;
    float s = 0.f;
    for (int si = 0; si < S; si++) s += Part[((size_t)si * Npad + n) * 128 + bb];
    float v = s + bias[n];
    Yt[idx] = v > 0.f ? v : 0.f;
}

__global__ void fc_reduce_out_kernel(const float* __restrict__ Part, const float* __restrict__ bias,
                                     float* __restrict__ out, int Nout, int Npad, int S) {
    int idx = blockIdx.x * blockDim.x + threadIdx.x;
    if (idx >= Nout * 128) return;
    int n = idx >> 7, bb = idx & 127;
    float s = 0.f;
    for (int si = 0; si < S; si++) s += Part[((size_t)si * Npad + n) * 128 + bb];
    out[(size_t)bb * Nout + n] = s + bias[n];
}

// ---------------- maxpools ---------------------------------------------------
__global__ void maxpool_kernel(const float* __restrict__ x, float* __restrict__ y,
                               int BC, int H, int W, int OH, int OW) {
    int idx = blockIdx.x * blockDim.x + threadIdx.x;
    int total = BC * OH * OW;
    if (idx >= total) return;
    int ox = idx % OW; int t = idx / OW;
    int oy = t % OH; int bc = t / OH;
    const float* p = x + ((size_t)bc * H + oy * 2) * W + ox * 2;
    float m = -INFINITY;
    #pragma unroll
    for (int i = 0; i < 3; i++)
        #pragma unroll
        for (int j = 0; j < 3; j++) {
            float v = p[i * W + j];
            m = v > m ? v : m;
        }
    y[idx] = m;
}

__global__ void maxpoolT_kernel(const float* __restrict__ x, float* __restrict__ yt,
                                int C, int H, int W, int OH, int OW) {
    int idx = blockIdx.x * blockDim.x + threadIdx.x;
    int total = 128 * C * OH * OW;
    if (idx >= total) return;
    int ox = idx % OW; int t = idx / OW;
    int oy = t % OH; t /= OH;
    int c = t % C; int b = t / C;
    const float* p = x + (((size_t)b * C + c) * H + oy * 2) * W + ox * 2;
    float m = -INFINITY;
    #pragma unroll
    for (int i = 0; i < 3; i++)
        #pragma unroll
        for (int j = 0; j < 3; j++) {
            float v = p[i * W + j];
            m = v > m ? v : m;
        }
    yt[((size_t)(c * OH + oy) * OW + ox) * 128 + b] = m;
}

// ---------------- driver -----------------------------------------------------
static inline int ceil_div(int a, int b) { return (a + b - 1) / b; }

extern "C" void kernel_launch(void* const* d_in, const int* in_sizes, int n_in,
                              void* d_out, int out_size) {
    const float* x = (const float*)d_in[0];
    const float *w[5], *bexp[5], *rw[5], *rb[5];
    for (int l = 0; l < 5; l++) {
        w[l]    = (const float*)d_in[1 + 4 * l];
        bexp[l] = (const float*)d_in[2 + 4 * l];
        rw[l]   = (const float*)d_in[3 + 4 * l];
        rb[l]   = (const float*)d_in[4 + 4 * l];
    }
    const float* fw1 = (const float*)d_in[21]; const float* fb1 = (const float*)d_in[22];
    const float* fw2 = (const float*)d_in[23]; const float* fb2 = (const float*)d_in[24];
    const float* fw3 = (const float*)d_in[25]; const float* fb3 = (const float*)d_in[26];

    float *bufA, *bufB, *wbuf, *pooled, *r;
    cudaGetSymbolAddress((void**)&bufA, g_bufA);
    cudaGetSymbolAddress((void**)&bufB, g_bufB);
    cudaGetSymbolAddress((void**)&wbuf, g_wbuf);
    cudaGetSymbolAddress((void**)&pooled, g_pooled);
    cudaGetSymbolAddress((void**)&r, g_r);

    const int B = 128;

    // ===== Layer 1: CondConv 3->64, k=11, s=4, p=2 : 224->55, pool->27
    pool_mean_kernel<<<dim3(3, B), 256>>>(x, pooled, 3, 224 * 224);
    routing_kernel<<<B, 256>>>(pooled, rw[0], rb[0], r, 3);
    {
        int ws4 = 64 * 3 * 121 / 4;
        mixw2_kernel<<<dim3(ceil_div(ws4, 256), B / 8), 256>>>((const float4*)w[0], r, (float4*)wbuf, ws4);
    }
    conv_ca_kernel<64, 128, 11, 11, 4, 2><<<dim3(24, 1, B), 128>>>(
        x, wbuf, r, bexp[0], bufA, 3, 64, 224, 224, 55, 55);
    maxpool_kernel<<<ceil_div(B * 64 * 27 * 27, 256), 256>>>(bufA, bufB, B * 64, 55, 55, 27, 27);

    // ===== Layer 2: CondConv 64->192, k=5, p=2 : 27->27, pool->13
    pool_mean_kernel<<<dim3(64, B), 256>>>(bufB, pooled, 64, 27 * 27);
    routing_kernel<<<B, 256>>>(pooled, rw[1], rb[1], r, 64);
    {
        int ws4 = 192 * 64 * 25 / 4;
        mixw2_kernel<<<dim3(ceil_div(ws4, 256), B / 8), 256>>>((const float4*)w[1], r, (float4*)wbuf, ws4);
    }
    conv_ca_kernel<64, 128, 5, 5, 1, 2><<<dim3(6, 3, B), 128>>>(
        bufB, wbuf, r, bexp[1], bufA, 64, 192, 27, 27, 27, 27);
    maxpool_kernel<<<ceil_div(B * 192 * 13 * 13, 256), 256>>>(bufA, bufB, B * 192, 27, 27, 13, 13);

    // ===== Layer 3: CondConv 192->384, k=3, p=1 : 13->13
    pool_mean_kernel<<<dim3(192, B), 256>>>(bufB, pooled, 192, 13 * 13);
    routing_kernel<<<B, 256>>>(pooled, rw[2], rb[2], r, 192);
    {
        int ws4 = 384 * 192 * 9 / 4;
        mixw2_kernel<<<dim3(ceil_div(ws4, 256), B / 8), 256>>>((const float4*)w[2], r, (float4*)wbuf, ws4);
    }
    conv_ca_kernel<128, 64, 3, 3, 1, 1><<<dim3(3, 3, B), 128>>>(
        bufB, wbuf, r, bexp[2], bufA, 192, 384, 13, 13, 13, 13);

    // ===== Layer 4: CondConv 384->256, k=3, p=1 : 13->13
    pool_mean_kernel<<<dim3(384, B), 256>>>(bufA, pooled, 384, 13 * 13);
    routing_kernel<<<B, 256>>>(pooled, rw[3], rb[3], r, 384);
    {
        int ws4 = 256 * 384 * 9 / 4;
        mixw2_kernel<<<dim3(ceil_div(ws4, 256), B / 8), 256>>>((const float4*)w[3], r, (float4*)wbuf, ws4);
    }
    conv_ca_kernel<128, 64, 3, 3, 1, 1><<<dim3(3, 2, B), 128>>>(
        bufA, wbuf, r, bexp[3], bufB, 384, 256, 13, 13, 13, 13);

    // ===== Layer 5: CondConv 256->256, k=3, p=1 : 13->13, pool->6
    pool_mean_kernel<<<dim3(256, B), 256>>>(bufB, pooled, 256, 13 * 13);
    routing_kernel<<<B, 256>>>(pooled, rw[4], rb[4], r, 256);
    {
        int ws4 = 256 * 256 * 9 / 4;
        mixw2_kernel<<<dim3(ceil_div(ws4, 256), B / 8), 256>>>((const float4*)w[4], r, (float4*)wbuf, ws4);
    }
    conv_ca_kernel<128, 64, 3, 3, 1, 1><<<dim3(3, 2, B), 128>>>(
        bufB, wbuf, r, bexp[4], bufA, 256, 256, 13, 13, 13, 13);

    // final pool -> transposed activations [9216][128]
    maxpoolT_kernel<<<ceil_div(B * 256 * 36, 256), 256>>>(bufA, wbuf + POOLT_OFF, 256, 13, 13, 6, 6);

    // ===== FC head (fp32, split-K) ==========================================
    fc_partial_kernel<<<dim3(32, 8), 256>>>(fw1, wbuf + POOLT_OFF, wbuf + PART_OFF,
                                            4096, 4096, 1152);
    fc_reduce_kernel<<<ceil_div(4096 * 128, 256), 256>>>(wbuf + PART_OFF, fb1,
                                                         wbuf + Y1T_OFF, 4096, 4096, 8);
    fc_partial_kernel<<<dim3(32, 8), 256>>>(fw2, wbuf + Y1T_OFF, wbuf + PART_OFF,
                                            4096, 4096, 512);
    fc_reduce_kernel<<<ceil_div(4096 * 128, 256), 256>>>(wbuf + PART_OFF, fb2,
                                                         wbuf + Y2T_OFF, 4096, 4096, 8);
    fc_partial_kernel<<<dim3(8, 8), 256>>>(fw3, wbuf + Y2T_OFF, wbuf + PART_OFF,
                                           1000, 1024, 512);
    fc_reduce_out_kernel<<<ceil_div(1000 * 128, 256), 256>>>(wbuf + PART_OFF, fb3,
                                                             (float*)d_out, 1000, 1024, 8);
}